// round 1
// baseline (speedup 1.0000x reference)
#include <cuda_runtime.h>

#define BATCH 4
#define CSEM 128
#define NPIX 4096
#define EPS 1e-6f
#define ATTN_SCALE 0.0625f   // 1/sqrt(256)
#define FULLMASK 0xFFFFFFFFu

// ---------------- scratch (device globals: allocation-free) ----------------
__device__ float g_edge32[BATCH * CSEM * 1024];
__device__ float g_fused32[BATCH * CSEM * 1024];
__device__ float g_edge_up[BATCH * CSEM * NPIX];
__device__ float g_fused_up[BATCH * CSEM * NPIX];
__device__ float g_sim[BATCH * NPIX];
__device__ float g_l2e[BATCH * NPIX];
__device__ float g_density[BATCH * NPIX];
__device__ float g_q[BATCH * NPIX * 256];
__device__ float g_k[BATCH * NPIX * 256];
__device__ float g_v[BATCH * NPIX * 256];
__device__ float g_ao[BATCH * NPIX * 256];
__device__ float g_wq2T[128 * 256];  // folded w_q, transposed [c][o]
__device__ float g_wkT[256 * 256];   // w_k transposed [c][o]
__device__ float g_wfT[256 * 128];   // w_fusion transposed [c][o]

// ---------------- weight prep: fold w_q, transpose all ----------------
__global__ void prep_weights_kernel(const float* __restrict__ w_q,
                                    const float* __restrict__ w_k,
                                    const float* __restrict__ w_f) {
    int i = blockIdx.x * 256 + threadIdx.x;   // 0..65535
    int o = i >> 8, c = i & 255;
    g_wkT[c * 256 + o] = w_k[o * 256 + c];
    if (c < 128) g_wq2T[c * 256 + o] = w_q[o * 256 + c] + w_q[o * 256 + 128 + c];
    if (o < 128) g_wfT[c * 128 + o] = w_f[o * 256 + c];
}

// ---------------- 1x1 conv at 32x32 (commutes with bilinear) ----------------
__global__ void conv32_kernel(const float* __restrict__ x,
                              const float* __restrict__ w,
                              const float* __restrict__ bias,
                              int Cin, int which) {
    int p = blockIdx.x * blockDim.x + threadIdx.x;  // 0..1023
    int o = blockIdx.y, b = blockIdx.z;
    const float* xb = x + (size_t)b * Cin * 1024 + p;
    const float* wr = w + o * Cin;
    float acc = bias[o];
    for (int c = 0; c < Cin; c++) acc = fmaf(wr[c], xb[(size_t)c * 1024], acc);
    float* out = which ? g_fused32 : g_edge32;
    out[((size_t)(b * CSEM + o)) * 1024 + p] = acc;
}

// ---------------- bilinear 32 -> 64 (align_corners=False) ----------------
__global__ void upsample_kernel() {
    int n = blockIdx.x * blockDim.x + threadIdx.x;  // 0..4095
    int c = blockIdx.y, b = blockIdx.z;
    int x = n >> 6, y = n & 63;
    float sx = x * 0.5f - 0.25f;
    int ix = (int)floorf(sx);
    float fx = sx - (float)ix;
    int x0 = min(max(ix, 0), 31), x1 = min(max(ix + 1, 0), 31);
    float sy = y * 0.5f - 0.25f;
    int iy = (int)floorf(sy);
    float fy = sy - (float)iy;
    int y0 = min(max(iy, 0), 31), y1 = min(max(iy + 1, 0), 31);
    float w00 = (1.f - fx) * (1.f - fy), w01 = (1.f - fx) * fy;
    float w10 = fx * (1.f - fy), w11 = fx * fy;
    size_t base = (size_t)(b * CSEM + c) * 1024;
    const float* e = g_edge32 + base;
    float ve = w00 * e[x0 * 32 + y0] + w01 * e[x0 * 32 + y1]
             + w10 * e[x1 * 32 + y0] + w11 * e[x1 * 32 + y1];
    const float* f = g_fused32 + base;
    float vf = w00 * f[x0 * 32 + y0] + w01 * f[x0 * 32 + y1]
             + w10 * f[x1 * 32 + y0] + w11 * f[x1 * 32 + y1];
    size_t ob = (size_t)(b * CSEM + c) * NPIX + n;
    g_edge_up[ob] = ve;
    g_fused_up[ob] = vf;
}

// ---------------- per-pixel: l2_edge + cosine similarity ----------------
__global__ void sim_kernel(const float* __restrict__ sem) {
    int n = blockIdx.x * blockDim.x + threadIdx.x;
    int b = blockIdx.y;
    size_t base = (size_t)b * CSEM * NPIX + n;
    float se = 0.f, ss = 0.f, dt = 0.f;
    for (int c = 0; c < CSEM; c++) {
        float e = g_edge_up[base + (size_t)c * NPIX];
        float s = sem[base + (size_t)c * NPIX];
        se = fmaf(e, e, se);
        ss = fmaf(s, s, ss);
        dt = fmaf(e, s, dt);
    }
    float le = sqrtf(se), ls = sqrtf(ss);
    g_l2e[b * NPIX + n] = le;
    g_sim[b * NPIX + n] = (dt / ((le + EPS) * (ls + EPS)) + 1.f) * 0.5f;
}

// ---------------- per-batch softmax over 4096 -> density ----------------
__global__ void density_kernel() {
    int b = blockIdx.x, t = threadIdx.x;
    int lane = t & 31, wid = t >> 5;
    __shared__ float smx[32], ssm[32];
    float v[4];
#pragma unroll
    for (int i = 0; i < 4; i++) v[i] = g_l2e[b * NPIX + t + i * 1024];
    float mx = fmaxf(fmaxf(v[0], v[1]), fmaxf(v[2], v[3]));
#pragma unroll
    for (int off = 16; off; off >>= 1) mx = fmaxf(mx, __shfl_xor_sync(FULLMASK, mx, off));
    if (!lane) smx[wid] = mx;
    __syncthreads();
    if (wid == 0) {
        float m = smx[lane];
#pragma unroll
        for (int off = 16; off; off >>= 1) m = fmaxf(m, __shfl_xor_sync(FULLMASK, m, off));
        smx[lane] = m;
    }
    __syncthreads();
    mx = smx[0];
    float e[4], s = 0.f;
#pragma unroll
    for (int i = 0; i < 4; i++) { e[i] = expf(v[i] - mx); s += e[i]; }
#pragma unroll
    for (int off = 16; off; off >>= 1) s += __shfl_xor_sync(FULLMASK, s, off);
    if (!lane) ssm[wid] = s;
    __syncthreads();
    if (wid == 0) {
        float x = ssm[lane];
#pragma unroll
        for (int off = 16; off; off >>= 1) x += __shfl_xor_sync(FULLMASK, x, off);
        ssm[lane] = x;
    }
    __syncthreads();
    float sc = 4096.f / ssm[0];
#pragma unroll
    for (int i = 0; i < 4; i++) g_density[b * NPIX + t + i * 1024] = e[i] * sc;
}

// ---------------- build V = concat(sem_raw, fused) pixel-major ----------------
__global__ void vbuild_kernel(const float* __restrict__ sem) {
    __shared__ float tile[32][33];
    int b = blockIdx.z;
    int n0 = blockIdx.x * 32;
    int cb = blockIdx.y;  // 0..7 (0-3: sem, 4-7: fused)
    int c0 = cb * 32;
    const float* src = (cb < 4) ? (sem + ((size_t)b * CSEM + c0) * NPIX)
                                : (g_fused_up + ((size_t)b * CSEM + (c0 - 128)) * NPIX);
    int tx = threadIdx.x, ty = threadIdx.y;
    for (int i = ty; i < 32; i += 8)
        tile[i][tx] = src[(size_t)i * NPIX + n0 + tx];
    __syncthreads();
    for (int i = ty; i < 32; i += 8)
        g_v[((size_t)b * NPIX + n0 + i) * 256 + c0 + tx] = tile[tx][i];
}

// ---------------- q/k projection: smem-tiled matvec, 32 pixels/block ----------------
__global__ __launch_bounds__(256) void qk_kernel(const float* __restrict__ sem,
                                                 const float* __restrict__ b_q,
                                                 const float* __restrict__ b_k) {
    __shared__ float sq[128 * 32];   // edge_t
    __shared__ float sk[256 * 32];   // sem_t ; fused_t
    int b = blockIdx.y, n0 = blockIdx.x * 32, tid = threadIdx.x;
    for (int idx = tid; idx < 128 * 32; idx += 256) {
        int c = idx >> 5, p = idx & 31;
        int n = n0 + p;
        size_t gi = (size_t)(b * CSEM + c) * NPIX + n;
        sq[idx] = g_edge_up[gi] * g_sim[b * NPIX + n];
        sk[idx] = sem[gi] * g_density[b * NPIX + n];
        sk[4096 + idx] = g_fused_up[gi];
    }
    __syncthreads();
    int o = tid;
    float accq[32], acck[32];
    float bq = b_q[o], bk = b_k[o];
#pragma unroll
    for (int p = 0; p < 32; p++) { accq[p] = bq; acck[p] = bk; }
    for (int c = 0; c < 128; c++) {
        float w = g_wq2T[c * 256 + o];
        const float4* r = (const float4*)(sq + c * 32);
#pragma unroll
        for (int j = 0; j < 8; j++) {
            float4 v = r[j];
            accq[4 * j + 0] = fmaf(w, v.x, accq[4 * j + 0]);
            accq[4 * j + 1] = fmaf(w, v.y, accq[4 * j + 1]);
            accq[4 * j + 2] = fmaf(w, v.z, accq[4 * j + 2]);
            accq[4 * j + 3] = fmaf(w, v.w, accq[4 * j + 3]);
        }
    }
    for (int c = 0; c < 256; c++) {
        float w = g_wkT[c * 256 + o];
        const float4* r = (const float4*)(sk + c * 32);
#pragma unroll
        for (int j = 0; j < 8; j++) {
            float4 v = r[j];
            acck[4 * j + 0] = fmaf(w, v.x, acck[4 * j + 0]);
            acck[4 * j + 1] = fmaf(w, v.y, acck[4 * j + 1]);
            acck[4 * j + 2] = fmaf(w, v.z, acck[4 * j + 2]);
            acck[4 * j + 3] = fmaf(w, v.w, acck[4 * j + 3]);
        }
    }
    size_t ob = ((size_t)b * NPIX + n0) * 256 + o;
#pragma unroll
    for (int p = 0; p < 32; p++) {
        g_q[ob + (size_t)p * 256] = accq[p];
        g_k[ob + (size_t)p * 256] = acck[p];
    }
}

// ---------------- local windowed attention: 1 warp / query ----------------
__global__ void attn_kernel() {
    int b = blockIdx.y;
    int warp = threadIdx.x >> 5, lane = threadIdx.x & 31;
    int n = blockIdx.x * 8 + warp;
    int qx = n >> 6, qy = n & 63;
    __shared__ float slog[8][128];
    const float* qrow = g_q + ((size_t)b * NPIX + n) * 256 + lane;
    float qr[8];
#pragma unroll
    for (int j = 0; j < 8; j++) qr[j] = qrow[32 * j] * ATTN_SCALE;
    int x0 = max(qx - 5, 0), x1 = min(qx + 5, 63);
    int y0 = max(qy - 5, 0), y1 = min(qy + 5, 63);
    float mx = -1e30f;
    int cnt = 0;
    for (int rx = x0; rx <= x1; rx++)
        for (int ry = y0; ry <= y1; ry++) {
            const float* kr = g_k + ((size_t)b * NPIX + (rx << 6) + ry) * 256 + lane;
            float d = 0.f;
#pragma unroll
            for (int j = 0; j < 8; j++) d = fmaf(qr[j], kr[32 * j], d);
#pragma unroll
            for (int off = 16; off; off >>= 1) d += __shfl_xor_sync(FULLMASK, d, off);
            if (!lane) slog[warp][cnt] = d;
            mx = fmaxf(mx, d);
            cnt++;
        }
    __syncwarp();
    float acc[8] = {0.f, 0.f, 0.f, 0.f, 0.f, 0.f, 0.f, 0.f};
    float sum = 0.f;
    cnt = 0;
    for (int rx = x0; rx <= x1; rx++)
        for (int ry = y0; ry <= y1; ry++) {
            float p = expf(slog[warp][cnt] - mx);
            cnt++;
            sum += p;
            const float* vr = g_v + ((size_t)b * NPIX + (rx << 6) + ry) * 256 + lane;
#pragma unroll
            for (int j = 0; j < 8; j++) acc[j] = fmaf(p, vr[32 * j], acc[j]);
        }
    float inv = 1.f / sum;
    float* orow = g_ao + ((size_t)b * NPIX + n) * 256 + lane;
#pragma unroll
    for (int j = 0; j < 8; j++) orow[32 * j] = acc[j] * inv;
}

// ---------------- fusion 1x1 conv -> d_out [b,128,64,64] ----------------
__global__ __launch_bounds__(128) void fusion_kernel(const float* __restrict__ b_f,
                                                     float* __restrict__ out) {
    __shared__ float sin_[256 * 36];
    int b = blockIdx.y, n0 = blockIdx.x * 32, tid = threadIdx.x;
    for (int idx = tid; idx < 32 * 256; idx += 128) {
        int p = idx >> 8, c = idx & 255;
        sin_[c * 36 + p] = g_ao[((size_t)b * NPIX + n0 + p) * 256 + c];
    }
    __syncthreads();
    float acc[32];
    float bo = b_f[tid];
#pragma unroll
    for (int p = 0; p < 32; p++) acc[p] = bo;
    for (int c = 0; c < 256; c++) {
        float w = g_wfT[c * 128 + tid];
        const float4* r = (const float4*)(sin_ + c * 36);
#pragma unroll
        for (int j = 0; j < 8; j++) {
            float4 v = r[j];
            acc[4 * j + 0] = fmaf(w, v.x, acc[4 * j + 0]);
            acc[4 * j + 1] = fmaf(w, v.y, acc[4 * j + 1]);
            acc[4 * j + 2] = fmaf(w, v.z, acc[4 * j + 2]);
            acc[4 * j + 3] = fmaf(w, v.w, acc[4 * j + 3]);
        }
    }
    __syncthreads();
#pragma unroll
    for (int p = 0; p < 32; p++) sin_[tid * 33 + p] = acc[p];
    __syncthreads();
    for (int idx = tid; idx < 128 * 32; idx += 128) {
        int o = idx >> 5, p = idx & 31;
        out[((size_t)(b * CSEM + o)) * NPIX + n0 + p] = sin_[o * 33 + p];
    }
}

// ---------------- launch ----------------
extern "C" void kernel_launch(void* const* d_in, const int* in_sizes, int n_in,
                              void* d_out, int out_size) {
    const float* edge   = (const float*)d_in[0];
    const float* sem    = (const float*)d_in[1];
    const float* fusedf = (const float*)d_in[2];
    const float* w_al   = (const float*)d_in[3];
    const float* b_al   = (const float*)d_in[4];
    const float* w_fal  = (const float*)d_in[5];
    const float* b_fal  = (const float*)d_in[6];
    const float* w_q    = (const float*)d_in[7];
    const float* b_q    = (const float*)d_in[8];
    const float* w_k    = (const float*)d_in[9];
    const float* b_k    = (const float*)d_in[10];
    const float* w_f    = (const float*)d_in[11];
    const float* b_f    = (const float*)d_in[12];
    float* out = (float*)d_out;

    prep_weights_kernel<<<256, 256>>>(w_q, w_k, w_f);
    conv32_kernel<<<dim3(4, 128, 4), 256>>>(edge, w_al, b_al, 64, 0);
    conv32_kernel<<<dim3(4, 128, 4), 256>>>(fusedf, w_fal, b_fal, 128, 1);
    upsample_kernel<<<dim3(16, 128, 4), 256>>>();
    sim_kernel<<<dim3(16, 4), 256>>>(sem);
    density_kernel<<<4, 1024>>>();
    vbuild_kernel<<<dim3(128, 8, 4), dim3(32, 8)>>>(sem);
    qk_kernel<<<dim3(128, 4), 256>>>(sem, b_q, b_k);
    attn_kernel<<<dim3(512, 4), 256>>>();
    fusion_kernel<<<dim3(128, 4), 128>>>(b_f, out);
}

// round 2
// speedup vs baseline: 1.0632x; 1.0632x over previous
#include <cuda_runtime.h>

#define BATCH 4
#define CSEM 128
#define NPIX 4096
#define EPS 1e-6f
#define ATTN_SCALE 0.0625f   // 1/sqrt(256)
#define FULLMASK 0xFFFFFFFFu

typedef unsigned long long ull;

// ---------------- scratch (device globals: allocation-free) ----------------
__device__ float g_edge32[BATCH * CSEM * 1024];
__device__ float g_fused32[BATCH * CSEM * 1024];
__device__ float g_edge_up[BATCH * CSEM * NPIX];
__device__ float g_fused_up[BATCH * CSEM * NPIX];
__device__ float g_sim[BATCH * NPIX];
__device__ float g_l2e[BATCH * NPIX];
__device__ float g_density[BATCH * NPIX];
__device__ float g_q[BATCH * NPIX * 256];
__device__ float g_k[BATCH * NPIX * 256];
__device__ float g_v[BATCH * NPIX * 256];
__device__ float g_ao[BATCH * NPIX * 256];
__device__ float g_wq2D[128 * 512];  // folded w_q, transposed, duplicated pairs [c][2o]
__device__ float g_wkD[256 * 512];   // w_k transposed, dup
__device__ float g_wfD[256 * 256];   // w_fusion transposed, dup

// ---------------- f32x2 packed FMA ----------------
__device__ __forceinline__ ull ffma2(ull a, ull b, ull c) {
    ull d;
    asm("fma.rn.f32x2 %0, %1, %2, %3;" : "=l"(d) : "l"(a), "l"(b), "l"(c));
    return d;
}
__device__ __forceinline__ float2 u2f(ull u) {
    union { ull u; float2 f; } t; t.u = u; return t.f;
}
__device__ __forceinline__ ull fdup(float x) {
    union { ull u; float2 f; } t; t.f.x = x; t.f.y = x; return t.u;
}

// ---------------- weight prep: fold w_q, transpose, duplicate ----------------
__global__ void prep_weights_kernel(const float* __restrict__ w_q,
                                    const float* __restrict__ w_k,
                                    const float* __restrict__ w_f) {
    int i = blockIdx.x * 256 + threadIdx.x;   // 0..65535
    int o = i >> 8, c = i & 255;
    float vk = w_k[o * 256 + c];
    g_wkD[c * 512 + 2 * o] = vk;
    g_wkD[c * 512 + 2 * o + 1] = vk;
    if (c < 128) {
        float vq = w_q[o * 256 + c] + w_q[o * 256 + 128 + c];
        g_wq2D[c * 512 + 2 * o] = vq;
        g_wq2D[c * 512 + 2 * o + 1] = vq;
    }
    if (o < 128) {
        float vf = w_f[o * 256 + c];
        g_wfD[c * 256 + 2 * o] = vf;
        g_wfD[c * 256 + 2 * o + 1] = vf;
    }
}

// ---------------- 1x1 conv at 32x32 (commutes with bilinear) ----------------
__global__ void conv32_kernel(const float* __restrict__ x,
                              const float* __restrict__ w,
                              const float* __restrict__ bias,
                              int Cin, int which) {
    int p = blockIdx.x * blockDim.x + threadIdx.x;  // 0..1023
    int o = blockIdx.y, b = blockIdx.z;
    const float* xb = x + (size_t)b * Cin * 1024 + p;
    const float* wr = w + o * Cin;
    float acc = bias[o];
    for (int c = 0; c < Cin; c++) acc = fmaf(wr[c], xb[(size_t)c * 1024], acc);
    float* out = which ? g_fused32 : g_edge32;
    out[((size_t)(b * CSEM + o)) * 1024 + p] = acc;
}

// ---------------- bilinear 32 -> 64, 8 channels per block ----------------
__global__ void upsample_kernel() {
    int n = blockIdx.x * 256 + threadIdx.x;  // 0..4095
    int cb = blockIdx.y, b = blockIdx.z;     // cb: 0..15 (8 ch each)
    int x = n >> 6, y = n & 63;
    float sx = x * 0.5f - 0.25f;
    int ix = (int)floorf(sx);
    float fx = sx - (float)ix;
    int x0 = min(max(ix, 0), 31), x1 = min(max(ix + 1, 0), 31);
    float sy = y * 0.5f - 0.25f;
    int iy = (int)floorf(sy);
    float fy = sy - (float)iy;
    int y0 = min(max(iy, 0), 31), y1 = min(max(iy + 1, 0), 31);
    float w00 = (1.f - fx) * (1.f - fy), w01 = (1.f - fx) * fy;
    float w10 = fx * (1.f - fy), w11 = fx * fy;
    int i00 = x0 * 32 + y0, i01 = x0 * 32 + y1;
    int i10 = x1 * 32 + y0, i11 = x1 * 32 + y1;
    size_t ib = (size_t)(b * CSEM + cb * 8) * 1024;
    size_t ob = (size_t)(b * CSEM + cb * 8) * NPIX + n;
#pragma unroll
    for (int cc = 0; cc < 8; cc++) {
        const float* e = g_edge32 + ib + (size_t)cc * 1024;
        g_edge_up[ob + (size_t)cc * NPIX] =
            w00 * e[i00] + w01 * e[i01] + w10 * e[i10] + w11 * e[i11];
        const float* f = g_fused32 + ib + (size_t)cc * 1024;
        g_fused_up[ob + (size_t)cc * NPIX] =
            w00 * f[i00] + w01 * f[i01] + w10 * f[i10] + w11 * f[i11];
    }
}

// ---------------- per-pixel: l2_edge + cosine similarity ----------------
__global__ void sim_kernel(const float* __restrict__ sem) {
    int n = blockIdx.x * blockDim.x + threadIdx.x;
    int b = blockIdx.y;
    size_t base = (size_t)b * CSEM * NPIX + n;
    float se = 0.f, ss = 0.f, dt = 0.f;
    for (int c = 0; c < CSEM; c++) {
        float e = g_edge_up[base + (size_t)c * NPIX];
        float s = sem[base + (size_t)c * NPIX];
        se = fmaf(e, e, se);
        ss = fmaf(s, s, ss);
        dt = fmaf(e, s, dt);
    }
    float le = sqrtf(se), ls = sqrtf(ss);
    g_l2e[b * NPIX + n] = le;
    g_sim[b * NPIX + n] = (dt / ((le + EPS) * (ls + EPS)) + 1.f) * 0.5f;
}

// ---------------- per-batch softmax over 4096 -> density ----------------
__global__ void density_kernel() {
    int b = blockIdx.x, t = threadIdx.x;
    int lane = t & 31, wid = t >> 5;
    __shared__ float smx[32], ssm[32];
    float v[4];
#pragma unroll
    for (int i = 0; i < 4; i++) v[i] = g_l2e[b * NPIX + t + i * 1024];
    float mx = fmaxf(fmaxf(v[0], v[1]), fmaxf(v[2], v[3]));
#pragma unroll
    for (int off = 16; off; off >>= 1) mx = fmaxf(mx, __shfl_xor_sync(FULLMASK, mx, off));
    if (!lane) smx[wid] = mx;
    __syncthreads();
    if (wid == 0) {
        float m = smx[lane];
#pragma unroll
        for (int off = 16; off; off >>= 1) m = fmaxf(m, __shfl_xor_sync(FULLMASK, m, off));
        smx[lane] = m;
    }
    __syncthreads();
    mx = smx[0];
    float e[4], s = 0.f;
#pragma unroll
    for (int i = 0; i < 4; i++) { e[i] = expf(v[i] - mx); s += e[i]; }
#pragma unroll
    for (int off = 16; off; off >>= 1) s += __shfl_xor_sync(FULLMASK, s, off);
    if (!lane) ssm[wid] = s;
    __syncthreads();
    if (wid == 0) {
        float x = ssm[lane];
#pragma unroll
        for (int off = 16; off; off >>= 1) x += __shfl_xor_sync(FULLMASK, x, off);
        ssm[lane] = x;
    }
    __syncthreads();
    float sc = 4096.f / ssm[0];
#pragma unroll
    for (int i = 0; i < 4; i++) g_density[b * NPIX + t + i * 1024] = e[i] * sc;
}

// ---------------- build V = concat(sem_raw, fused) pixel-major ----------------
__global__ void vbuild_kernel(const float* __restrict__ sem) {
    __shared__ float tile[32][33];
    int b = blockIdx.z;
    int n0 = blockIdx.x * 32;
    int cb = blockIdx.y;  // 0..7 (0-3: sem, 4-7: fused)
    int c0 = cb * 32;
    const float* src = (cb < 4) ? (sem + ((size_t)b * CSEM + c0) * NPIX)
                                : (g_fused_up + ((size_t)b * CSEM + (c0 - 128)) * NPIX);
    int tx = threadIdx.x, ty = threadIdx.y;
    for (int i = ty; i < 32; i += 8)
        tile[i][tx] = src[(size_t)i * NPIX + n0 + tx];
    __syncthreads();
    for (int i = ty; i < 32; i += 8)
        g_v[((size_t)b * NPIX + n0 + i) * 256 + c0 + tx] = tile[tx][i];
}

// ---------------- q/k projection: f32x2 packed matvec, 32 pixels/block ----------------
__global__ __launch_bounds__(256) void qk_kernel(const float* __restrict__ sem,
                                                 const float* __restrict__ b_q,
                                                 const float* __restrict__ b_k) {
    __shared__ float sq[128 * 32];   // edge_t
    __shared__ float sk[256 * 32];   // sem_t ; fused_t
    int b = blockIdx.y, n0 = blockIdx.x * 32, tid = threadIdx.x;
    for (int idx = tid; idx < 128 * 32; idx += 256) {
        int c = idx >> 5, p = idx & 31;
        int n = n0 + p;
        size_t gi = (size_t)(b * CSEM + c) * NPIX + n;
        sq[idx] = g_edge_up[gi] * g_sim[b * NPIX + n];
        sk[idx] = sem[gi] * g_density[b * NPIX + n];
        sk[4096 + idx] = g_fused_up[gi];
    }
    __syncthreads();
    int o = tid;
    ull accq[16], acck[16];
    ull bq = fdup(b_q[o]), bk = fdup(b_k[o]);
#pragma unroll
    for (int j = 0; j < 16; j++) { accq[j] = bq; acck[j] = bk; }
#pragma unroll 4
    for (int c = 0; c < 128; c++) {
        ull w = *(const ull*)&g_wq2D[c * 512 + 2 * o];
        const ulonglong2* r = (const ulonglong2*)&sq[c * 32];
#pragma unroll
        for (int j = 0; j < 8; j++) {
            ulonglong2 v = r[j];
            accq[2 * j] = ffma2(w, v.x, accq[2 * j]);
            accq[2 * j + 1] = ffma2(w, v.y, accq[2 * j + 1]);
        }
    }
#pragma unroll 4
    for (int c = 0; c < 256; c++) {
        ull w = *(const ull*)&g_wkD[c * 512 + 2 * o];
        const ulonglong2* r = (const ulonglong2*)&sk[c * 32];
#pragma unroll
        for (int j = 0; j < 8; j++) {
            ulonglong2 v = r[j];
            acck[2 * j] = ffma2(w, v.x, acck[2 * j]);
            acck[2 * j + 1] = ffma2(w, v.y, acck[2 * j + 1]);
        }
    }
    size_t ob = ((size_t)b * NPIX + n0) * 256 + o;
#pragma unroll
    for (int j = 0; j < 16; j++) {
        float2 fq = u2f(accq[j]), fk = u2f(acck[j]);
        g_q[ob + (size_t)(2 * j) * 256] = fq.x;
        g_q[ob + (size_t)(2 * j + 1) * 256] = fq.y;
        g_k[ob + (size_t)(2 * j) * 256] = fk.x;
        g_k[ob + (size_t)(2 * j + 1) * 256] = fk.y;
    }
}

// ---------------- local windowed attention: register-tiled smem GEMM ----------------
// Block: 4x4 query tile (16 queries), padded 16x16 key window (256 keys).
// Thread (qg,kg): qg=t>>6 (qx offset), kg=t&63 (4-key group). 4q x 4k logits in regs.
#define ATTN_SMEM_FLOATS (16384 + 8192 + 2048 + 32)
#define KS_AT(c, ki) ((c) * 256 + ((ki) ^ ((((c) >> 2) & 7) << 2)))

__global__ __launch_bounds__(256, 2) void attn_kernel() {
    extern __shared__ float sm[];
    float* KV = sm;                  // 64 x 256 (K chunk [c][ki] swizzled / V chunk [kil][ch])
    float* Ps = sm + 16384;          // [q][512]: dup pairs per key
    float* Qs = sm + 16384 + 8192;   // [c][32]: dup pairs per query, scaled
    float* red = sm + 16384 + 8192 + 2048;  // 16 q x 2 halves

    int t = threadIdx.x, b = blockIdx.y, tile = blockIdx.x;
    int qx0 = (tile >> 4) << 2, qy0 = (tile & 15) << 2;
    int kx0 = qx0 - 5, ky0 = qy0 - 5;
    int qg = t >> 6, kg = t & 63;
    int half = (t >> 5) & 1;
    size_t kvbase = (size_t)b * NPIX * 256;

    // ---- QK: logits ----
    ull accl[4][2];
#pragma unroll
    for (int qi = 0; qi < 4; qi++) { accl[qi][0] = 0ull; accl[qi][1] = 0ull; }

    for (int cc = 0; cc < 4; cc++) {
        __syncthreads();
        // stage K chunk: 64ch x 256 keys, transposed [c][ki], swizzled
#pragma unroll
        for (int it = 0; it < 16; it++) {
            int idx = it * 256 + t;
            int ki = idx >> 4, cg = idx & 15;
            int kr = ki >> 4, kc = ki & 15;
            int kx = min(max(kx0 + kr, 0), 63), ky = min(max(ky0 + kc, 0), 63);
            int nk = (kx << 6) + ky;
            float4 v = *(const float4*)&g_k[kvbase + (size_t)nk * 256 + cc * 64 + cg * 4];
            int c0 = cg * 4;
            KV[KS_AT(c0 + 0, ki)] = v.x;
            KV[KS_AT(c0 + 1, ki)] = v.y;
            KV[KS_AT(c0 + 2, ki)] = v.z;
            KV[KS_AT(c0 + 3, ki)] = v.w;
        }
        // stage Q chunk: 16 q x 64 ch, dup pairs, scaled
#pragma unroll
        for (int j = 0; j < 4; j++) {
            int idx = j * 256 + t;
            int q = idx >> 6, c = idx & 63;
            int nq = ((qx0 + (q >> 2)) << 6) + qy0 + (q & 3);
            float qv = g_q[kvbase + (size_t)nq * 256 + cc * 64 + c] * ATTN_SCALE;
            Qs[c * 32 + 2 * q] = qv;
            Qs[c * 32 + 2 * q + 1] = qv;
        }
        __syncthreads();
#pragma unroll 8
        for (int c = 0; c < 64; c++) {
            int kidx = (kg * 4) ^ (((c >> 2) & 7) << 2);
            ulonglong2 kk = *(const ulonglong2*)&KV[c * 256 + kidx];
            const float* qrow = &Qs[c * 32];
#pragma unroll
            for (int qi = 0; qi < 4; qi++) {
                ull qd = *(const ull*)&qrow[2 * (qg * 4 + qi)];
                accl[qi][0] = ffma2(qd, kk.x, accl[qi][0]);
                accl[qi][1] = ffma2(qd, kk.y, accl[qi][1]);
            }
        }
    }

    // ---- unpack + mask ----
    float lg[4][4];
    int kr = kg >> 2;
    int kxA = kx0 + kr;
#pragma unroll
    for (int qi = 0; qi < 4; qi++) {
        float2 a = u2f(accl[qi][0]), bb = u2f(accl[qi][1]);
        lg[qi][0] = a.x; lg[qi][1] = a.y; lg[qi][2] = bb.x; lg[qi][3] = bb.y;
        bool rok = (kr >= qg) && (kr <= qg + 10) && (kxA >= 0) && (kxA < 64);
#pragma unroll
        for (int kj = 0; kj < 4; kj++) {
            int kc = (kg & 3) * 4 + kj;
            int kyA = ky0 + kc;
            bool ok = rok && (kc >= qi) && (kc <= qi + 10) && (kyA >= 0) && (kyA < 64);
            if (!ok) lg[qi][kj] = -1e30f;
        }
    }

    // ---- softmax across the 64 kg-threads (2 warps) per query row ----
    float mx[4];
#pragma unroll
    for (int qi = 0; qi < 4; qi++) {
        float m = fmaxf(fmaxf(lg[qi][0], lg[qi][1]), fmaxf(lg[qi][2], lg[qi][3]));
#pragma unroll
        for (int off = 16; off; off >>= 1) m = fmaxf(m, __shfl_xor_sync(FULLMASK, m, off));
        if ((t & 31) == 0) red[(qg * 4 + qi) * 2 + half] = m;
    }
    __syncthreads();
#pragma unroll
    for (int qi = 0; qi < 4; qi++)
        mx[qi] = fmaxf(red[(qg * 4 + qi) * 2], red[(qg * 4 + qi) * 2 + 1]);
    __syncthreads();
    float pv[4][4];
#pragma unroll
    for (int qi = 0; qi < 4; qi++) {
        float s = 0.f;
#pragma unroll
        for (int kj = 0; kj < 4; kj++) {
            pv[qi][kj] = __expf(lg[qi][kj] - mx[qi]);
            s += pv[qi][kj];
        }
#pragma unroll
        for (int off = 16; off; off >>= 1) s += __shfl_xor_sync(FULLMASK, s, off);
        if ((t & 31) == 0) red[(qg * 4 + qi) * 2 + half] = s;
    }
    __syncthreads();
#pragma unroll
    for (int qi = 0; qi < 4; qi++) {
        float inv = 1.f / (red[(qg * 4 + qi) * 2] + red[(qg * 4 + qi) * 2 + 1]);
        int q = qg * 4 + qi;
#pragma unroll
        for (int kj = 0; kj < 4; kj++) {
            int ki = kg * 4 + kj;
            float p = pv[qi][kj] * inv;
            Ps[q * 512 + ki * 2] = p;
            Ps[q * 512 + ki * 2 + 1] = p;
        }
    }

    // ---- AV: out[16q][256ch] = P[16q][256k] @ V[256k][256ch] ----
    ull acco[4][2];
#pragma unroll
    for (int qi = 0; qi < 4; qi++) { acco[qi][0] = 0ull; acco[qi][1] = 0ull; }
    int chg = kg;  // channel group: 4 channels per thread

    for (int kc4 = 0; kc4 < 4; kc4++) {
        __syncthreads();
        // stage V chunk: 64 keys x 256 ch, [kil][ch]
#pragma unroll
        for (int it = 0; it < 16; it++) {
            int idx = it * 256 + t;
            int kil = idx >> 6, cg = idx & 63;
            int ki = kc4 * 64 + kil;
            int kr2 = ki >> 4, kc2 = ki & 15;
            int kx = min(max(kx0 + kr2, 0), 63), ky = min(max(ky0 + kc2, 0), 63);
            int nk = (kx << 6) + ky;
            *(float4*)&KV[kil * 256 + cg * 4] =
                *(const float4*)&g_v[kvbase + (size_t)nk * 256 + cg * 4];
        }
        __syncthreads();
#pragma unroll 8
        for (int kil = 0; kil < 64; kil++) {
            int ki = kc4 * 64 + kil;
            ulonglong2 vv = *(const ulonglong2*)&KV[kil * 256 + chg * 4];
#pragma unroll
            for (int qi = 0; qi < 4; qi++) {
                ull pd = *(const ull*)&Ps[(qg * 4 + qi) * 512 + ki * 2];
                acco[qi][0] = ffma2(pd, vv.x, acco[qi][0]);
                acco[qi][1] = ffma2(pd, vv.y, acco[qi][1]);
            }
        }
    }

    // ---- write out ----
#pragma unroll
    for (int qi = 0; qi < 4; qi++) {
        int q = qg * 4 + qi;
        int nq = ((qx0 + (q >> 2)) << 6) + qy0 + (q & 3);
        ull* dst = (ull*)&g_ao[kvbase + (size_t)nq * 256 + chg * 4];
        dst[0] = acco[qi][0];
        dst[1] = acco[qi][1];
    }
}

// ---------------- fusion 1x1 conv -> d_out [b,128,64,64] ----------------
__global__ __launch_bounds__(128) void fusion_kernel(const float* __restrict__ b_f,
                                                     float* __restrict__ out) {
    __shared__ float sin_[256 * 36];
    int b = blockIdx.y, n0 = blockIdx.x * 32, tid = threadIdx.x;
    for (int idx = tid; idx < 32 * 256; idx += 128) {
        int p = idx >> 8, c = idx & 255;
        sin_[c * 36 + p] = g_ao[((size_t)b * NPIX + n0 + p) * 256 + c];
    }
    __syncthreads();
    ull acc[16];
    ull bo = fdup(b_f[tid]);
#pragma unroll
    for (int j = 0; j < 16; j++) acc[j] = bo;
#pragma unroll 4
    for (int c = 0; c < 256; c++) {
        ull w = *(const ull*)&g_wfD[c * 256 + 2 * tid];
        const float* row = &sin_[c * 36];
#pragma unroll
        for (int j = 0; j < 8; j++) {
            ulonglong2 v = *(const ulonglong2*)&row[j * 4];
            acc[2 * j] = ffma2(w, v.x, acc[2 * j]);
            acc[2 * j + 1] = ffma2(w, v.y, acc[2 * j + 1]);
        }
    }
    __syncthreads();
#pragma unroll
    for (int j = 0; j < 16; j++) {
        float2 f = u2f(acc[j]);
        sin_[tid * 33 + 2 * j] = f.x;
        sin_[tid * 33 + 2 * j + 1] = f.y;
    }
    __syncthreads();
    for (int idx = tid; idx < 128 * 32; idx += 128) {
        int o = idx >> 5, p = idx & 31;
        out[((size_t)(b * CSEM + o)) * NPIX + n0 + p] = sin_[o * 33 + p];
    }
}

// ---------------- launch ----------------
extern "C" void kernel_launch(void* const* d_in, const int* in_sizes, int n_in,
                              void* d_out, int out_size) {
    const float* edge   = (const float*)d_in[0];
    const float* sem    = (const float*)d_in[1];
    const float* fusedf = (const float*)d_in[2];
    const float* w_al   = (const float*)d_in[3];
    const float* b_al   = (const float*)d_in[4];
    const float* w_fal  = (const float*)d_in[5];
    const float* b_fal  = (const float*)d_in[6];
    const float* w_q    = (const float*)d_in[7];
    const float* b_q    = (const float*)d_in[8];
    const float* w_k    = (const float*)d_in[9];
    const float* b_k    = (const float*)d_in[10];
    const float* w_f    = (const float*)d_in[11];
    const float* b_f    = (const float*)d_in[12];
    float* out = (float*)d_out;

    int attn_smem = ATTN_SMEM_FLOATS * 4;
    cudaFuncSetAttribute(attn_kernel, cudaFuncAttributeMaxDynamicSharedMemorySize, attn_smem);

    prep_weights_kernel<<<256, 256>>>(w_q, w_k, w_f);
    conv32_kernel<<<dim3(4, 128, 4), 256>>>(edge, w_al, b_al, 64, 0);
    conv32_kernel<<<dim3(4, 128, 4), 256>>>(fusedf, w_fal, b_fal, 128, 1);
    upsample_kernel<<<dim3(16, 16, 4), 256>>>();
    sim_kernel<<<dim3(16, 4), 256>>>(sem);
    density_kernel<<<4, 1024>>>();
    vbuild_kernel<<<dim3(128, 8, 4), dim3(32, 8)>>>(sem);
    qk_kernel<<<dim3(128, 4), 256>>>(sem, b_q, b_k);
    attn_kernel<<<dim3(256, 4), 256, attn_smem>>>();
    fusion_kernel<<<dim3(128, 4), 128>>>(b_f, out);
}